// round 1
// baseline (speedup 1.0000x reference)
#include <cuda_runtime.h>

#define LAYERS   8
#define WIDTH    128
#define DDIM     64
#define KNOTS    8
#define PPD      23          // 3*KNOTS-1
#define BATCH    16384
#define TB       64          // batch rows per CTA
#define NTHREADS 256
#define DG       16          // dims per chunk
#define NCHUNK   (DDIM/DG)   // 4
#define WSROWS   (DG*PPD)    // 368
#define WSPAD    68          // padded row stride (floats) for smem weight tile
#define BI       4.0f

// shared memory layout (float offsets)
#define OFF_X0   0
#define OFF_X1   (TB*DDIM)                  // 4096
#define OFF_H    (2*TB*DDIM)                // 8192
#define OFF_WS   (2*TB*DDIM + TB*WIDTH)     // 16384
#define SMEM_FLOATS (OFF_WS + WSROWS*WSPAD) // 16384 + 25024 = 41408
#define SMEM_BYTES  (SMEM_FLOATS*4)         // 165632 B

// Pre-masked weights (static device scratch — no runtime allocation)
__device__ float g_W1m[2*LAYERS*WIDTH*DDIM];
__device__ float g_Wom[2*LAYERS*DDIM*PPD*WIDTH];

// ---------------------------------------------------------------------------
// Prep: apply MADE masks to W1 and Wout once per launch.
//   m1[w][i]  keep iff i <= (w % 63)
//   m2[o][w]  keep iff (w % 63) < (o / PPD)
// ---------------------------------------------------------------------------
__global__ void prep_kernel(const float* __restrict__ fW1, const float* __restrict__ fWo,
                            const float* __restrict__ gW1, const float* __restrict__ gWo)
{
    const int N1 = LAYERS*WIDTH*DDIM;       // 65536 per flow
    const int N2 = LAYERS*DDIM*PPD*WIDTH;   // 1507328 per flow
    const int stride = gridDim.x * blockDim.x;
    for (int i = blockIdx.x*blockDim.x + threadIdx.x; i < 2*N1; i += stride) {
        int fl = i / N1, j = i - fl*N1;
        int w = (j >> 6) & (WIDTH-1);
        int c = j & (DDIM-1);
        const float* s = fl ? gW1 : fW1;
        g_W1m[i] = (c <= (w % (DDIM-1))) ? s[j] : 0.f;
    }
    for (int i = blockIdx.x*blockDim.x + threadIdx.x; i < 2*N2; i += stride) {
        int fl = i / N2, j = i - fl*N2;
        int w = j & (WIDTH-1);
        int o = (j >> 7) % (DDIM*PPD);
        int d = o / PPD;
        const float* s = fl ? gWo : fWo;
        g_Wom[i] = ((w % (DDIM-1)) < d) ? s[j] : 0.f;
    }
}

// ---------------------------------------------------------------------------
// Rational-quadratic spline for one scalar given its 23 params.
// Fully unrolled; no dynamically-indexed arrays (keeps everything in regs).
// ---------------------------------------------------------------------------
__device__ __forceinline__ void rqs_eval(const float par[PPD], float xraw,
                                         float& xout, float& ldj)
{
    const float C1 = 8.0f / 1.01f;      // (2*BI)/(1+adj)
    const float CADJ = 0.00125f;        // SOFTMAX_ADJ/KNOTS

    // softmax (max-subtracted) for widths / heights
    float mw = par[0];
#pragma unroll
    for (int j = 1; j < 8; j++) mw = fmaxf(mw, par[j]);
    float ew[8]; float sw = 0.f;
#pragma unroll
    for (int j = 0; j < 8; j++) { ew[j] = __expf(par[j] - mw); sw += ew[j]; }
    float isw = __frcp_rn(sw);

    float mh = par[8];
#pragma unroll
    for (int j = 1; j < 8; j++) mh = fmaxf(mh, par[8+j]);
    float eh[8]; float sh = 0.f;
#pragma unroll
    for (int j = 0; j < 8; j++) { eh[j] = __expf(par[8+j] - mh); sh += eh[j]; }
    float ish = __frcp_rn(sh);

    // softplus derivatives (interior knots)
    float sd[7];
#pragma unroll
    for (int j = 0; j < 7; j++) {
        float v = par[16+j];
        float sp = (v > 15.f) ? v : log1pf(__expf(v));
        sd[j] = sp + 0.001f;
    }

    float xc = fminf(fmaxf(xraw, -BI), BI);

    // scan bins; select the one containing xc (predicated, unrolled)
    float xl = -BI, yl = -BI;
    float xk = 0.f, xk1 = 1.f, yk = 0.f, yk1 = 1.f, dk = 1.f, dk1 = 1.f;
    bool found = false;
#pragma unroll
    for (int j = 0; j < 8; j++) {
        float wj = (ew[j]*isw + CADJ) * C1;
        float hj = (eh[j]*ish + CADJ) * C1;
        float xr2 = xl + wj;
        float yr2 = yl + hj;
        bool sel = (!found) && ((xc < xr2) || (j == 7));
        if (sel) {
            xk = xl; xk1 = xr2; yk = yl; yk1 = yr2;
            dk  = (j == 0) ? 1.f : sd[j-1];
            dk1 = (j == 7) ? 1.f : sd[j];
            found = true;
        }
        xl = xr2; yl = yr2;
    }

    float invdx = __frcp_rn(xk1 - xk);
    float dyv = yk1 - yk;
    float sk  = dyv * invdx;
    float xi  = (xc - xk) * invdx;
    float omx = 1.f - xi;
    float xiomx = xi * omx;
    float den = sk + (dk1 + dk - 2.f*sk) * xiomx;
    float invden = __frcp_rn(den);
    float nume = sk*xi*xi + dk*xiomx;
    float outv = yk + dyv * nume * invden;
    float ldn = dk1*xi*xi + 2.f*sk*xiomx + dk*omx*omx;
    float ld = 2.f*__logf(sk) + __logf(ldn) - 2.f*__logf(den);

    bool inside = (xraw > -BI) && (xraw < BI);
    xout = inside ? outv : xraw;
    ldj  = inside ? ld : 0.f;
}

// ---------------------------------------------------------------------------
// Main kernel: one CTA processes TB=64 rows through all 8 layers.
// blockIdx.y selects flow (0 = x/f, 1 = y/g).
// ---------------------------------------------------------------------------
__global__ __launch_bounds__(NTHREADS, 1)
void maf_kernel(const float* __restrict__ xin_f, const float* __restrict__ xin_g,
                const float* __restrict__ f_b1, const float* __restrict__ f_bout,
                const float* __restrict__ g_b1, const float* __restrict__ g_bout,
                float* __restrict__ out)
{
    extern __shared__ float sm[];
    const int tid  = threadIdx.x;
    const int flow = blockIdx.y;
    const int row0 = blockIdx.x * TB;

    const float* xin   = flow ? xin_g  : xin_f;
    const float* b1g   = flow ? g_b1   : f_b1;
    const float* boutg = flow ? g_bout : f_bout;
    const float* W1m   = g_W1m + flow * (LAYERS*WIDTH*DDIM);
    const float* Wom   = g_Wom + flow * (LAYERS*DDIM*PPD*WIDTH);

    // load batch tile: X[r][d], row-major matches global layout
    for (int i = tid; i < TB*DDIM; i += NTHREADS)
        sm[OFF_X0 + i] = xin[row0*DDIM + i];

    const int dl = tid & 15;   // dim-local within chunk
    const int rg = tid >> 4;   // row group 0..15
    const int r0 = rg * 4;

    float ldacc[4] = {0.f, 0.f, 0.f, 0.f};
    int cur = OFF_X0, nxt = OFF_X1;

    __syncthreads();

    for (int layer = 0; layer < LAYERS; layer++) {
        // ---- stage masked W1 into smem (reuses WS area), [w][WSPAD]
        const float* W1l = W1m + layer*WIDTH*DDIM;
        for (int i = tid; i < WIDTH*DDIM/4; i += NTHREADS) {
            int w = i >> 4, c4 = i & 15;
            float4 v = ((const float4*)W1l)[i];
            *(float4*)&sm[OFF_WS + w*WSPAD + c4*4] = v;
        }
        __syncthreads();

        // ---- GEMM1: H = relu(X @ W1m^T + b1)
        for (int it = 0; it < (TB*WIDTH)/NTHREADS; it++) {
            int idx = tid + it*NTHREADS;
            int r = idx >> 7, w = idx & (WIDTH-1);
            float a = b1g[layer*WIDTH + w];
            const float* xr = &sm[cur + r*DDIM];
            const float* wr = &sm[OFF_WS + w*WSPAD];
#pragma unroll
            for (int iv = 0; iv < 16; iv++) {
                float4 xv = *(const float4*)&xr[iv*4];
                float4 wv = *(const float4*)&wr[iv*4];
                a += xv.x*wv.x + xv.y*wv.y + xv.z*wv.z + xv.w*wv.w;
            }
            sm[OFF_H + idx] = fmaxf(a, 0.f);
        }
        __syncthreads();

        // ---- GEMM2 + spline, chunked over dims (16 dims, K split in halves)
        for (int chunk = 0; chunk < NCHUNK; chunk++) {
            const int d0 = chunk * DG;
            const int d  = d0 + dl;

            float acc[4][PPD];
#pragma unroll
            for (int ri = 0; ri < 4; ri++)
#pragma unroll
                for (int p = 0; p < PPD; p++) acc[ri][p] = 0.f;

            const float* Wol = Wom + (layer*DDIM*PPD + d0*PPD) * WIDTH;

            for (int kh = 0; kh < 2; kh++) {
                // stage WS: 368 rows x 64 cols of Wout (this k-half)
                for (int i = tid; i < WSROWS*16; i += NTHREADS) {
                    int rr = i >> 4, c4 = i & 15;
                    float4 v = *(const float4*)&Wol[rr*WIDTH + kh*64 + c4*4];
                    *(float4*)&sm[OFF_WS + rr*WSPAD + c4*4] = v;
                }
                __syncthreads();

                const float* hs0 = &sm[OFF_H + (r0+0)*WIDTH + kh*64];
                const float* hs1 = &sm[OFF_H + (r0+1)*WIDTH + kh*64];
                const float* hs2 = &sm[OFF_H + (r0+2)*WIDTH + kh*64];
                const float* hs3 = &sm[OFF_H + (r0+3)*WIDTH + kh*64];
                const float* wsp = &sm[OFF_WS + dl*PPD*WSPAD];

                for (int wv = 0; wv < 16; wv++) {
                    float4 h0 = *(const float4*)&hs0[wv*4];
                    float4 h1 = *(const float4*)&hs1[wv*4];
                    float4 h2 = *(const float4*)&hs2[wv*4];
                    float4 h3 = *(const float4*)&hs3[wv*4];
#pragma unroll
                    for (int p = 0; p < PPD; p++) {
                        float4 w4 = *(const float4*)&wsp[p*WSPAD + wv*4];
                        acc[0][p] += h0.x*w4.x + h0.y*w4.y + h0.z*w4.z + h0.w*w4.w;
                        acc[1][p] += h1.x*w4.x + h1.y*w4.y + h1.z*w4.z + h1.w*w4.w;
                        acc[2][p] += h2.x*w4.x + h2.y*w4.y + h2.z*w4.z + h2.w*w4.w;
                        acc[3][p] += h3.x*w4.x + h3.y*w4.y + h3.z*w4.z + h3.w*w4.w;
                    }
                }
                __syncthreads();
            }

            // ---- spline epilogue: 4 rows, this thread's dim d
            const float* bo = boutg + (layer*DDIM + d)*PPD;
            float bor[PPD];
#pragma unroll
            for (int p = 0; p < PPD; p++) bor[p] = bo[p];

#pragma unroll
            for (int ri = 0; ri < 4; ri++) {
                int r = r0 + ri;
                float par[PPD];
#pragma unroll
                for (int p = 0; p < PPD; p++) par[p] = acc[ri][p] + bor[p];
                float xraw = sm[cur + r*DDIM + d];
                float xo2, ldj;
                rqs_eval(par, xraw, xo2, ldj);
                sm[nxt + r*DDIM + (DDIM-1 - d)] = xo2;  // reversal fused here
                ldacc[ri] += ldj;
            }
        }

        // swap x buffers; next-layer W1 stage + its sync orders the spline
        // writes before GEMM1 reads of the new X
        int t = cur; cur = nxt; nxt = t;
    }

    __syncthreads();  // all spline writes of final layer complete

    // ---- outputs: [xo (B*64) | ldf (B) | yo (B*64) | ldg (B)]
    const int xbase  = flow ? (BATCH*DDIM + BATCH) : 0;
    const int ldbase = flow ? (2*BATCH*DDIM + BATCH) : (BATCH*DDIM);

    for (int i = tid; i < TB*DDIM; i += NTHREADS)
        out[xbase + row0*DDIM + i] = sm[cur + i];

    // log-det reduction over the 16 dim-classes per row (reuse WS area)
    float* red = &sm[OFF_WS];
#pragma unroll
    for (int ri = 0; ri < 4; ri++)
        red[(r0+ri)*16 + dl] = ldacc[ri];
    __syncthreads();
    if (tid < TB) {
        float s = 0.f;
#pragma unroll
        for (int j = 0; j < 16; j++) s += red[tid*16 + j];
        out[ldbase + row0 + tid] = s;
    }
}

// ---------------------------------------------------------------------------
extern "C" void kernel_launch(void* const* d_in, const int* in_sizes, int n_in,
                              void* d_out, int out_size)
{
    const float* x      = (const float*)d_in[0];
    const float* y      = (const float*)d_in[1];
    const float* f_W1   = (const float*)d_in[2];
    const float* f_b1   = (const float*)d_in[3];
    const float* f_Wout = (const float*)d_in[4];
    const float* f_bout = (const float*)d_in[5];
    const float* g_W1   = (const float*)d_in[6];
    const float* g_b1   = (const float*)d_in[7];
    const float* g_Wout = (const float*)d_in[8];
    const float* g_bout = (const float*)d_in[9];
    float* out = (float*)d_out;

    cudaFuncSetAttribute(maf_kernel, cudaFuncAttributeMaxDynamicSharedMemorySize, SMEM_BYTES);

    prep_kernel<<<1024, 256>>>(f_W1, f_Wout, g_W1, g_Wout);

    dim3 grid(BATCH/TB, 2);
    maf_kernel<<<grid, NTHREADS, SMEM_BYTES>>>(x, y, f_b1, f_bout, g_b1, g_bout, out);
}